// round 11
// baseline (speedup 1.0000x reference)
#include <cuda_runtime.h>
#include <math.h>

#define BB  8
#define NN  325
#define FIN 32
#define TT  24
#define HH  4
#define CC  32
#define HC  128
#define KMAX 8

// -------- scratch (device globals; no allocation allowed) --------
__device__ float g_Wh  [(size_t)BB * TT * NN * HC];   // [b][t][n][o]  ~32MB
__device__ float g_f1  [(size_t)BB * TT * NN * HH];   // [b][t][n][h]
__device__ float g_f2  [(size_t)BB * TT * NN * HH];
__device__ float g_Sall[(size_t)BB * TT * HC];        // [bt][o]
__device__ int   g_nidx[NN * KMAX];
__device__ float g_nw  [NN * KMAX];
__device__ int   g_ncnt[NN];

// ================= K0: constrain weights + neighbor compaction =================
// One warp per row i. Deterministic (ballot-ordered, j ascending).
__global__ void k0_neighbors(const float* __restrict__ iw,
                             const float* __restrict__ base,
                             const float* __restrict__ mask) {
    int i    = blockIdx.x;
    int lane = threadIdx.x;
    __shared__ int   s_idx[KMAX];
    __shared__ float s_val[KMAX];

    float s   = 0.f;
    int   cnt = 0;
    for (int jb = 0; jb < NN; jb += 32) {
        int j = jb + lane;
        float m = 0.f, mv = 0.f;
        if (j < NN) {
            m = mask[i * NN + j];
            float w  = iw  [i * NN + j];
            float bb = base[i * NN + j];
            float v = fminf(fmaxf(w, 0.5f * bb), 1.5f * bb);
            v = fmaxf(v, 0.f);
            mv = v * m;
        }
        s += mv;
        unsigned bal = __ballot_sync(0xffffffffu, m != 0.f);
        if (m != 0.f) {
            int pos = cnt + __popc(bal & ((1u << lane) - 1u));
            if (pos < KMAX) { s_idx[pos] = j; s_val[pos] = mv; }
        }
        cnt += __popc(bal);
    }
    #pragma unroll
    for (int off = 16; off; off >>= 1) s += __shfl_xor_sync(0xffffffffu, s, off);
    if (s == 0.f) s = 1e-6f;
    __syncwarp();

    cnt = min(cnt, KMAX);
    if (lane == 0) g_ncnt[i] = cnt;
    if (lane < cnt) {
        g_nidx[i * KMAX + lane] = s_idx[lane];
        g_nw  [i * KMAX + lane] = s_val[lane] / s;
    }
}

// ================= K1: Wh = xp @ W^T + b, fused f1/f2 =================
// Block = (b, n); 128 threads = output feature o. x staged in smem (broadcast
// LDS.128 along t), W row in registers. 768 FFMA/thread.
__global__ void __launch_bounds__(HC) k1_wh(const float* __restrict__ x,
                                            const float* __restrict__ Ww,
                                            const float* __restrict__ Wb,
                                            const float* __restrict__ attn) {
    int blk = blockIdx.x;
    int b = blk / NN, n = blk % NN;
    int o = threadIdx.x;             // 0..127
    int h = o >> 5, c = o & 31;

    __shared__ __align__(16) float x_sm[FIN * TT];   // [f][t], rows 96B-aligned
    __shared__ float W_sm[HC * 33];                  // padded: bank-conflict-free

    const float* xb = x + ((size_t)b * NN + n) * (FIN * TT);
    for (int idx = o; idx < FIN * TT; idx += HC) x_sm[idx] = xb[idx];
    for (int idx = o; idx < HC * FIN; idx += HC) {
        int oo = idx >> 5, ff = idx & 31;
        W_sm[oo * 33 + ff] = Ww[idx];
    }
    __syncthreads();

    float wreg[FIN];
    #pragma unroll
    for (int f = 0; f < FIN; f++) wreg[f] = W_sm[o * 33 + f];
    float bias = Wb[o];

    float acc[TT];
    #pragma unroll
    for (int t = 0; t < TT; t++) acc[t] = bias;

    #pragma unroll
    for (int f = 0; f < FIN; f++) {
        float wv = wreg[f];
        const float4* xr = (const float4*)&x_sm[f * TT];
        #pragma unroll
        for (int q = 0; q < TT / 4; q++) {
            float4 v = xr[q];
            acc[q*4+0] = fmaf(v.x, wv, acc[q*4+0]);
            acc[q*4+1] = fmaf(v.y, wv, acc[q*4+1]);
            acc[q*4+2] = fmaf(v.z, wv, acc[q*4+2]);
            acc[q*4+3] = fmaf(v.w, wv, acc[q*4+3]);
        }
    }

    float a1 = attn[h * (2 * CC) + c];
    float a2 = attn[h * (2 * CC) + CC + c];

    #pragma unroll
    for (int t = 0; t < TT; t++) {
        size_t wbase = ((size_t)(b * TT + t) * NN + n) * HC;
        g_Wh[wbase + o] = acc[t];
        float v1 = acc[t] * a1;
        float v2 = acc[t] * a2;
        #pragma unroll
        for (int off = 16; off; off >>= 1) {
            v1 += __shfl_xor_sync(0xffffffffu, v1, off);
            v2 += __shfl_xor_sync(0xffffffffu, v2, off);
        }
        if (c == 0) {
            size_t fb = ((size_t)(b * TT + t) * NN + n) * HH + h;
            g_f1[fb] = v1;
            g_f2[fb] = v2;
        }
    }
}

// ================= K2: S_all[bt][o] = sum_n Wh[bt][n][o] =================
__global__ void __launch_bounds__(HC) k2_colsum() {
    int bt = blockIdx.x;
    int o  = threadIdx.x;
    const float* base = g_Wh + (size_t)bt * NN * HC + o;
    float a0 = 0.f, a1 = 0.f, a2 = 0.f, a3 = 0.f, a4 = 0.f;
    #pragma unroll 1
    for (int n = 0; n < NN; n += 5) {   // 325 = 5 * 65, MLP = 5
        a0 += base[(size_t)(n + 0) * HC];
        a1 += base[(size_t)(n + 1) * HC];
        a2 += base[(size_t)(n + 2) * HC];
        a3 += base[(size_t)(n + 3) * HC];
        a4 += base[(size_t)(n + 4) * HC];
    }
    g_Sall[(size_t)bt * HC + o] = ((a0 + a1) + (a2 + a3)) + a4;
}

// ================= K3: sparse softmax + weighted sum + transpose =================
// Block = (b, i); 128 threads = o. Loops over t; results staged in smem and
// written coalesced as out[b][i][o][t].
__global__ void __launch_bounds__(HC) k3_out(float* __restrict__ out) {
    int blk = blockIdx.x;
    int b = blk / NN, i = blk % NN;
    int o = threadIdx.x;
    int h = o >> 5;

    __shared__ float o_sm[HC * (TT + 1)];   // pad to 25 -> conflict-free

    int cnt = g_ncnt[i];
    int   jidx[KMAX];
    float jw[KMAX];
    #pragma unroll
    for (int k = 0; k < KMAX; k++) {
        jidx[k] = (k < cnt) ? g_nidx[i * KMAX + k] : 0;
        jw[k]   = (k < cnt) ? g_nw  [i * KMAX + k] : 0.f;
    }

    for (int t = 0; t < TT; t++) {
        int bt = b * TT + t;
        float f1i = g_f1[((size_t)bt * NN + i) * HH + h];

        float sarr[KMAX];
        float m = 0.f;   // max over {0, scores}: non-neighbor scores are exactly 0
        #pragma unroll
        for (int k = 0; k < KMAX; k++) {
            if (k < cnt) {
                float f2v = g_f2[((size_t)bt * NN + jidx[k]) * HH + h];
                float e = f1i + f2v;
                float lr = (e > 0.f) ? e : 0.2f * e;   // leaky_relu, slope 0.2
                sarr[k] = lr + jw[k];
                m = fmaxf(m, sarr[k]);
            }
        }
        float E0    = expf(-m);
        float denom = (float)(NN - cnt) * E0;
        float acc   = E0 * g_Sall[(size_t)bt * HC + o];
        #pragma unroll
        for (int k = 0; k < KMAX; k++) {
            if (k < cnt) {
                float Ek = expf(sarr[k] - m);
                denom += Ek;
                acc += (Ek - E0) * g_Wh[((size_t)bt * NN + jidx[k]) * HC + o];
            }
        }
        o_sm[o * (TT + 1) + t] = acc / denom;
    }
    __syncthreads();

    float* ob = out + ((size_t)b * NN + i) * (HC * TT);
    for (int idx = o; idx < HC * TT; idx += HC) {
        int oo = idx / TT, tt = idx - oo * TT;
        ob[idx] = o_sm[oo * (TT + 1) + tt];
    }
}

// ================= launch =================
extern "C" void kernel_launch(void* const* d_in, const int* in_sizes, int n_in,
                              void* d_out, int out_size) {
    const float* x    = (const float*)d_in[0];  // (B, N, F_IN, T)
    const float* Ww   = (const float*)d_in[1];  // (HC, F_IN)
    const float* Wb   = (const float*)d_in[2];  // (HC,)
    const float* attn = (const float*)d_in[3];  // (H, 2C)
    const float* iw   = (const float*)d_in[4];  // (N, N)
    const float* base = (const float*)d_in[5];  // (N, N)
    const float* mask = (const float*)d_in[6];  // (N, N)
    float* out = (float*)d_out;                 // (B, N, HC, T)
    (void)in_sizes; (void)n_in; (void)out_size;

    k0_neighbors<<<NN, 32>>>(iw, base, mask);
    k1_wh<<<BB * NN, HC>>>(x, Ww, Wb, attn);
    k2_colsum<<<BB * TT, HC>>>();
    k3_out<<<BB * NN, HC>>>(out);
}

// round 12
// speedup vs baseline: 2.0646x; 2.0646x over previous
#include <cuda_runtime.h>
#include <math.h>

#define BB  8
#define NN  325
#define FIN 32
#define TT  24
#define HH  4
#define CC  32
#define HC  128
#define KMAX 8

// -------- scratch (device globals; no allocation allowed) --------
__device__ float  g_Wh  [(size_t)BB * TT * NN * HC];   // [bt][n][o]  ~32MB
__device__ float  g_f1  [(size_t)BB * TT * NN * HH];   // [bt][n][h]
__device__ float  g_f2  [(size_t)BB * TT * NN * HH];
__device__ float  g_Sall[(size_t)BB * TT * HC];        // [bt][o]
__device__ float4 g_coef[(size_t)BB * TT * NN * HH];   // [bt][i][h] = {a0,c0,c1,c2}
__device__ int    g_nidx[NN * KMAX];
__device__ float  g_nw  [NN * KMAX];
__device__ int    g_ncnt[NN];

// ================= K0: constrain weights + neighbor compaction =================
__global__ void k0_neighbors(const float* __restrict__ iw,
                             const float* __restrict__ base,
                             const float* __restrict__ mask) {
    int i    = blockIdx.x;
    int lane = threadIdx.x;
    __shared__ int   s_idx[KMAX];
    __shared__ float s_val[KMAX];
    if (lane < KMAX) { s_idx[lane] = 0; s_val[lane] = 0.f; }
    __syncwarp();

    float s   = 0.f;
    int   cnt = 0;
    for (int jb = 0; jb < NN; jb += 32) {
        int j = jb + lane;
        float m = 0.f, mv = 0.f;
        if (j < NN) {
            m = mask[i * NN + j];
            float w  = iw  [i * NN + j];
            float bb = base[i * NN + j];
            float v = fminf(fmaxf(w, 0.5f * bb), 1.5f * bb);
            v = fmaxf(v, 0.f);
            mv = v * m;
        }
        s += mv;
        unsigned bal = __ballot_sync(0xffffffffu, m != 0.f);
        if (m != 0.f) {
            int pos = cnt + __popc(bal & ((1u << lane) - 1u));
            if (pos < KMAX) { s_idx[pos] = j; s_val[pos] = mv; }
        }
        cnt += __popc(bal);
    }
    #pragma unroll
    for (int off = 16; off; off >>= 1) s += __shfl_xor_sync(0xffffffffu, s, off);
    if (s == 0.f) s = 1e-6f;
    __syncwarp();

    cnt = min(cnt, KMAX);
    if (lane == 0) g_ncnt[i] = cnt;
    if (lane < KMAX) {
        g_nidx[i * KMAX + lane] = (lane < cnt) ? s_idx[lane] : 0;
        g_nw  [i * KMAX + lane] = (lane < cnt) ? s_val[lane] / s : 0.f;
    }
}

// ================= K1: Wh = xp @ W^T + b, fused f1/f2 =================
__global__ void __launch_bounds__(HC) k1_wh(const float* __restrict__ x,
                                            const float* __restrict__ Ww,
                                            const float* __restrict__ Wb,
                                            const float* __restrict__ attn) {
    int blk = blockIdx.x;
    int b = blk / NN, n = blk % NN;
    int o = threadIdx.x;             // 0..127
    int h = o >> 5, c = o & 31;

    __shared__ __align__(16) float x_sm[FIN * TT];
    __shared__ float W_sm[HC * 33];

    const float* xb = x + ((size_t)b * NN + n) * (FIN * TT);
    for (int idx = o; idx < FIN * TT; idx += HC) x_sm[idx] = xb[idx];
    for (int idx = o; idx < HC * FIN; idx += HC) {
        int oo = idx >> 5, ff = idx & 31;
        W_sm[oo * 33 + ff] = Ww[idx];
    }
    __syncthreads();

    float wreg[FIN];
    #pragma unroll
    for (int f = 0; f < FIN; f++) wreg[f] = W_sm[o * 33 + f];
    float bias = Wb[o];

    float acc[TT];
    #pragma unroll
    for (int t = 0; t < TT; t++) acc[t] = bias;

    #pragma unroll
    for (int f = 0; f < FIN; f++) {
        float wv = wreg[f];
        const float4* xr = (const float4*)&x_sm[f * TT];
        #pragma unroll
        for (int q = 0; q < TT / 4; q++) {
            float4 v = xr[q];
            acc[q*4+0] = fmaf(v.x, wv, acc[q*4+0]);
            acc[q*4+1] = fmaf(v.y, wv, acc[q*4+1]);
            acc[q*4+2] = fmaf(v.z, wv, acc[q*4+2]);
            acc[q*4+3] = fmaf(v.w, wv, acc[q*4+3]);
        }
    }

    float a1 = attn[h * (2 * CC) + c];
    float a2 = attn[h * (2 * CC) + CC + c];

    #pragma unroll
    for (int t = 0; t < TT; t++) {
        size_t wbase = ((size_t)(b * TT + t) * NN + n) * HC;
        g_Wh[wbase + o] = acc[t];
        float v1 = acc[t] * a1;
        float v2 = acc[t] * a2;
        #pragma unroll
        for (int off = 16; off; off >>= 1) {
            v1 += __shfl_xor_sync(0xffffffffu, v1, off);
            v2 += __shfl_xor_sync(0xffffffffu, v2, off);
        }
        if (c == 0) {
            size_t fb = ((size_t)(b * TT + t) * NN + n) * HH + h;
            g_f1[fb] = v1;
            g_f2[fb] = v2;
        }
    }
}

// ================= K2: S_all[bt][o] = sum_n Wh[bt][n][o] =================
// 512 threads: 4 slices of the n range, smem reduce.
__global__ void __launch_bounds__(512) k2_colsum() {
    int bt = blockIdx.x;
    int o  = threadIdx.x & 127;
    int q  = threadIdx.x >> 7;          // 0..3
    __shared__ float red[4][HC];

    int n0 = q * 82;
    int n1 = min(NN, n0 + 82);
    const float* base = g_Wh + (size_t)bt * NN * HC + o;
    float a0 = 0.f, a1 = 0.f;
    int n = n0;
    for (; n + 1 < n1; n += 2) {
        a0 += base[(size_t)n * HC];
        a1 += base[(size_t)(n + 1) * HC];
    }
    if (n < n1) a0 += base[(size_t)n * HC];
    red[q][o] = a0 + a1;
    __syncthreads();
    if (q == 0)
        g_Sall[(size_t)bt * HC + o] = (red[0][o] + red[1][o]) + (red[2][o] + red[3][o]);
}

// ================= K3a: attention coefficients per (bt, i, h) =================
// out[bt][i][o] = a0 * Sall[bt][o] + sum_k ck * Wh[bt][jk][o]
#define NCOEF (BB * TT * NN * HH)
__global__ void __launch_bounds__(256) k3a_coef() {
    int idx = blockIdx.x * 256 + threadIdx.x;
    if (idx >= NCOEF) return;
    int h  = idx & 3;
    int r  = idx >> 2;            // r = bt*NN + i
    int i  = r % NN;
    int bt = r / NN;

    int cnt = min(g_ncnt[i], 3);
    float f1i = g_f1[(size_t)r * HH + h];

    float sarr[3];
    float m = 0.f;                 // non-neighbor scores are exactly 0
    #pragma unroll
    for (int k = 0; k < 3; k++) {
        if (k < cnt) {
            int j = g_nidx[i * KMAX + k];
            float e  = f1i + g_f2[((size_t)bt * NN + j) * HH + h];
            float lr = (e > 0.f) ? e : 0.2f * e;
            sarr[k] = lr + g_nw[i * KMAX + k];
            m = fmaxf(m, sarr[k]);
        } else sarr[k] = 0.f;
    }
    float E0 = expf(-m);
    float Ek[3];
    float denom = (float)(NN - cnt) * E0;
    #pragma unroll
    for (int k = 0; k < 3; k++) {
        Ek[k] = (k < cnt) ? expf(sarr[k] - m) : 0.f;
        denom += Ek[k];
    }
    float rd = 1.f / denom;
    float4 cf;
    cf.x = E0 * rd;
    cf.y = (0 < cnt) ? (Ek[0] - E0) * rd : 0.f;
    cf.z = (1 < cnt) ? (Ek[1] - E0) * rd : 0.f;
    cf.w = (2 < cnt) ? (Ek[2] - E0) * rd : 0.f;
    g_coef[(size_t)r * HH + h] = cf;
}

// ================= K3b: gather-FMA + transpose =================
// Block = (b,i), 768 threads = 24 warps; warp w handles t=w with float4 over o.
__global__ void __launch_bounds__(768) k3b_out(float* __restrict__ out) {
    int blk = blockIdx.x;
    int b = blk / NN, i = blk % NN;
    __shared__ float sm[TT * HC];      // [t][o] — conflict-free both ways

    int t = threadIdx.x >> 5;          // 0..23
    int l = threadIdx.x & 31;
    int h = l >> 3;                    // lane covers o = 4l..4l+3
    int bt = b * TT + t;

    int j0 = g_nidx[i * KMAX + 0];
    int j1 = g_nidx[i * KMAX + 1];
    int j2 = g_nidx[i * KMAX + 2];

    float4 cf = g_coef[((size_t)bt * NN + i) * HH + h];
    const float4* wh = (const float4*)(g_Wh + (size_t)bt * NN * HC);
    float4 s  = ((const float4*)(g_Sall + (size_t)bt * HC))[l];
    float4 w0 = wh[(size_t)j0 * 32 + l];
    float4 w1 = wh[(size_t)j1 * 32 + l];
    float4 w2 = wh[(size_t)j2 * 32 + l];

    float4 acc;
    acc.x = fmaf(cf.x, s.x, fmaf(cf.y, w0.x, fmaf(cf.z, w1.x, cf.w * w2.x)));
    acc.y = fmaf(cf.x, s.y, fmaf(cf.y, w0.y, fmaf(cf.z, w1.y, cf.w * w2.y)));
    acc.z = fmaf(cf.x, s.z, fmaf(cf.y, w0.z, fmaf(cf.z, w1.z, cf.w * w2.z)));
    acc.w = fmaf(cf.x, s.w, fmaf(cf.y, w0.w, fmaf(cf.z, w1.w, cf.w * w2.w)));
    ((float4*)&sm[t * HC])[l] = acc;
    __syncthreads();

    // transpose write: out[b][i][o][t], float4 along t (24 % 4 == 0)
    int g = threadIdx.x >> 7;          // 0..5
    int o = threadIdx.x & 127;
    float4 v;
    v.x = sm[(4 * g + 0) * HC + o];
    v.y = sm[(4 * g + 1) * HC + o];
    v.z = sm[(4 * g + 2) * HC + o];
    v.w = sm[(4 * g + 3) * HC + o];
    float* ob = out + ((size_t)(b * NN + i) * HC + o) * TT;
    ((float4*)ob)[g] = v;
}

// ================= launch =================
extern "C" void kernel_launch(void* const* d_in, const int* in_sizes, int n_in,
                              void* d_out, int out_size) {
    const float* x    = (const float*)d_in[0];  // (B, N, F_IN, T)
    const float* Ww   = (const float*)d_in[1];  // (HC, F_IN)
    const float* Wb   = (const float*)d_in[2];  // (HC,)
    const float* attn = (const float*)d_in[3];  // (H, 2C)
    const float* iw   = (const float*)d_in[4];  // (N, N)
    const float* base = (const float*)d_in[5];  // (N, N)
    const float* mask = (const float*)d_in[6];  // (N, N)
    float* out = (float*)d_out;                 // (B, N, HC, T)
    (void)in_sizes; (void)n_in; (void)out_size;

    k0_neighbors<<<NN, 32>>>(iw, base, mask);
    k1_wh<<<BB * NN, HC>>>(x, Ww, Wb, attn);
    k2_colsum<<<BB * TT, 512>>>();
    k3a_coef<<<(NCOEF + 255) / 256, 256>>>();
    k3b_out<<<BB * NN, 768>>>(out);
}

// round 13
// speedup vs baseline: 2.0882x; 1.0114x over previous
#include <cuda_runtime.h>
#include <math.h>

#define BB  8
#define NN  325
#define FIN 32
#define TT  24
#define HH  4
#define CC  32
#define HC  128
#define KMAX 8

// -------- scratch (device globals; no allocation allowed) --------
__device__ float  g_Wh  [(size_t)BB * TT * NN * HC];   // [bt][n][o]  ~32MB
__device__ float  g_f1  [(size_t)BB * TT * NN * HH];   // [bt][n][h]
__device__ float  g_f2  [(size_t)BB * TT * NN * HH];
__device__ float  g_Sall[(size_t)BB * TT * HC];        // [bt][o]
__device__ int    g_nidx[NN * KMAX];
__device__ float  g_nw  [NN * KMAX];
__device__ int    g_ncnt[NN];

// ================= K0: constrain weights + neighbor compaction =================
__global__ void k0_neighbors(const float* __restrict__ iw,
                             const float* __restrict__ base,
                             const float* __restrict__ mask) {
    int i    = blockIdx.x;
    int lane = threadIdx.x;
    __shared__ int   s_idx[KMAX];
    __shared__ float s_val[KMAX];
    if (lane < KMAX) { s_idx[lane] = 0; s_val[lane] = 0.f; }
    __syncwarp();

    float s   = 0.f;
    int   cnt = 0;
    for (int jb = 0; jb < NN; jb += 32) {
        int j = jb + lane;
        float m = 0.f, mv = 0.f;
        if (j < NN) {
            m = mask[i * NN + j];
            float w  = iw  [i * NN + j];
            float bb = base[i * NN + j];
            float v = fminf(fmaxf(w, 0.5f * bb), 1.5f * bb);
            v = fmaxf(v, 0.f);
            mv = v * m;
        }
        s += mv;
        unsigned bal = __ballot_sync(0xffffffffu, m != 0.f);
        if (m != 0.f) {
            int pos = cnt + __popc(bal & ((1u << lane) - 1u));
            if (pos < KMAX) { s_idx[pos] = j; s_val[pos] = mv; }
        }
        cnt += __popc(bal);
    }
    #pragma unroll
    for (int off = 16; off; off >>= 1) s += __shfl_xor_sync(0xffffffffu, s, off);
    if (s == 0.f) s = 1e-6f;
    __syncwarp();

    cnt = min(cnt, KMAX);
    if (lane == 0) g_ncnt[i] = cnt;
    if (lane < KMAX) {
        g_nidx[i * KMAX + lane] = (lane < cnt) ? s_idx[lane] : 0;
        g_nw  [i * KMAX + lane] = (lane < cnt) ? s_val[lane] / s : 0.f;
    }
}

// ================= K1: Wh = xp @ W^T + b; f1/f2 via folded vectors ==========
// f1[bt,n,h] = sum_f xp[f]*u1[h][f] + beta1[h], u1[h] = W[h*C+c,:]^T @ a1[h].
// No warp shuffles.
__global__ void __launch_bounds__(HC) k1_wh(const float* __restrict__ x,
                                            const float* __restrict__ Ww,
                                            const float* __restrict__ Wb,
                                            const float* __restrict__ attn) {
    int blk = blockIdx.x;
    int b = blk / NN, n = blk % NN;
    int o = threadIdx.x;             // 0..127

    __shared__ __align__(16) float x_sm[FIN * TT];   // [f][t]
    __shared__ float W_sm[HC * 33];                  // padded
    __shared__ float u1_sm[HC], u2_sm[HC];           // [h][f]
    __shared__ float beta_sm[8];                     // [sel][h]

    const float* xb = x + ((size_t)b * NN + n) * (FIN * TT);
    for (int idx = o; idx < FIN * TT; idx += HC) x_sm[idx] = xb[idx];
    for (int idx = o; idx < HC * FIN; idx += HC) {
        int oo = idx >> 5, ff = idx & 31;
        W_sm[oo * 33 + ff] = Ww[idx];
    }
    __syncthreads();

    float wreg[FIN];
    #pragma unroll
    for (int f = 0; f < FIN; f++) wreg[f] = W_sm[o * 33 + f];
    float bias = Wb[o];

    // u1/u2: thread o -> (h = o>>5, f = o&31)
    {
        int hh = o >> 5, f = o & 31;
        const float* arow = attn + hh * (2 * CC);
        float s1 = 0.f, s2 = 0.f;
        #pragma unroll
        for (int cc = 0; cc < CC; cc++) {
            float wv = W_sm[(hh * 32 + cc) * 33 + f];
            s1 = fmaf(wv, __ldg(&arow[cc]),      s1);
            s2 = fmaf(wv, __ldg(&arow[CC + cc]), s2);
        }
        u1_sm[o] = s1; u2_sm[o] = s2;
    }
    if (o < 8) {
        int sel = o >> 2, hh = o & 3;
        float bsum = 0.f;
        #pragma unroll
        for (int cc = 0; cc < CC; cc++)
            bsum = fmaf(__ldg(&Wb[hh * 32 + cc]),
                        __ldg(&attn[hh * (2 * CC) + sel * CC + cc]), bsum);
        beta_sm[o] = bsum;
    }

    // main GEMM: acc[t] over registers
    float acc[TT];
    #pragma unroll
    for (int t = 0; t < TT; t++) acc[t] = bias;

    #pragma unroll
    for (int f = 0; f < FIN; f++) {
        float wv = wreg[f];
        const float4* xr = (const float4*)&x_sm[f * TT];
        #pragma unroll
        for (int q = 0; q < TT / 4; q++) {
            float4 v = xr[q];
            acc[q*4+0] = fmaf(v.x, wv, acc[q*4+0]);
            acc[q*4+1] = fmaf(v.y, wv, acc[q*4+1]);
            acc[q*4+2] = fmaf(v.z, wv, acc[q*4+2]);
            acc[q*4+3] = fmaf(v.w, wv, acc[q*4+3]);
        }
    }

    #pragma unroll
    for (int t = 0; t < TT; t++)
        g_Wh[((size_t)(b * TT + t) * NN + n) * HC + o] = acc[t];

    __syncthreads();   // u_sm / beta_sm ready (also covered by time above)

    // f1/f2: 192 values = (sel in {0,1}) x (h in 0..3) x (t in 0..23)
    for (int idx = o; idx < 192; idx += HC) {
        int sel = idx / 96;
        int rem = idx - sel * 96;
        int t  = rem % 24;
        int hh = rem / 24;
        const float* u = sel ? &u2_sm[hh * 32] : &u1_sm[hh * 32];
        float v = beta_sm[sel * 4 + hh];
        #pragma unroll
        for (int f = 0; f < FIN; f++) v = fmaf(x_sm[f * TT + t], u[f], v);
        size_t fb = ((size_t)(b * TT + t) * NN + n) * HH + hh;
        if (sel) g_f2[fb] = v; else g_f1[fb] = v;
    }
}

// ================= K2: S_all[bt][o] = sum_n Wh[bt][n][o], LDG.128 ============
__global__ void __launch_bounds__(512) k2_colsum() {
    int bt = blockIdx.x;
    int l  = threadIdx.x & 31;       // float4 lane over o
    int q  = threadIdx.x >> 5;       // 0..15 n-slice
    __shared__ float4 red[16][32];

    int n0 = q * 21;
    int n1 = min(NN, n0 + 21);
    const float4* base = (const float4*)(g_Wh + (size_t)bt * NN * HC) + l;
    float4 a = make_float4(0.f, 0.f, 0.f, 0.f);
    for (int n = n0; n < n1; n++) {
        float4 v = base[(size_t)n * 32];
        a.x += v.x; a.y += v.y; a.z += v.z; a.w += v.w;
    }
    red[q][l] = a;
    __syncthreads();
    if (threadIdx.x < 32) {
        float4 s = red[0][l];
        #pragma unroll
        for (int k = 1; k < 16; k++) {
            float4 v = red[k][l];
            s.x += v.x; s.y += v.y; s.z += v.z; s.w += v.w;
        }
        ((float4*)(g_Sall + (size_t)bt * HC))[l] = s;
    }
}

// ================= K3: fused coef + gather-FMA + transpose ====================
// Block = (b,i), 768 threads = 24 warps (warp = t). Lanes 0..3 compute the
// per-h coefficient quad; shuffles broadcast; all lanes gather float4.
__global__ void __launch_bounds__(768) k3_out(float* __restrict__ out) {
    int blk = blockIdx.x;
    int b = blk / NN, i = blk % NN;
    __shared__ float sm[TT * HC];      // [t][o]

    int t = threadIdx.x >> 5;          // 0..23
    int l = threadIdx.x & 31;
    int bt = b * TT + t;

    int j0 = g_nidx[i * KMAX + 0];
    int j1 = g_nidx[i * KMAX + 1];
    int j2 = g_nidx[i * KMAX + 2];
    int cnt = min(g_ncnt[i], 3);

    // lanes 0..3: coefficients for h = l
    float4 cf = make_float4(0.f, 0.f, 0.f, 0.f);
    if (l < 4) {
        int h = l;
        float f1i = g_f1[((size_t)bt * NN + i) * HH + h];
        int   jj[3] = { j0, j1, j2 };
        float sarr[3];
        float m = 0.f;                 // non-neighbor scores are exactly 0
        #pragma unroll
        for (int k = 0; k < 3; k++) {
            if (k < cnt) {
                float e  = f1i + g_f2[((size_t)bt * NN + jj[k]) * HH + h];
                float lr = (e > 0.f) ? e : 0.2f * e;
                sarr[k] = lr + g_nw[i * KMAX + k];
                m = fmaxf(m, sarr[k]);
            } else sarr[k] = 0.f;
        }
        float E0 = __expf(-m) ;
        // use full-precision expf to stay safe on rel-err
        E0 = expf(-m);
        float Ek[3];
        float denom = (float)(NN - cnt) * E0;
        #pragma unroll
        for (int k = 0; k < 3; k++) {
            Ek[k] = (k < cnt) ? expf(sarr[k] - m) : 0.f;
            denom += Ek[k];
        }
        float rd = 1.f / denom;
        cf.x = E0 * rd;
        cf.y = (0 < cnt) ? (Ek[0] - E0) * rd : 0.f;
        cf.z = (1 < cnt) ? (Ek[1] - E0) * rd : 0.f;
        cf.w = (2 < cnt) ? (Ek[2] - E0) * rd : 0.f;
    }
    int hsrc = l >> 3;                 // lane's head
    unsigned full = 0xffffffffu;
    float a0 = __shfl_sync(full, cf.x, hsrc);
    float c0 = __shfl_sync(full, cf.y, hsrc);
    float c1 = __shfl_sync(full, cf.z, hsrc);
    float c2 = __shfl_sync(full, cf.w, hsrc);

    const float4* wh = (const float4*)(g_Wh + (size_t)bt * NN * HC);
    float4 s  = ((const float4*)(g_Sall + (size_t)bt * HC))[l];
    float4 w0 = wh[(size_t)j0 * 32 + l];
    float4 w1 = wh[(size_t)j1 * 32 + l];
    float4 w2 = wh[(size_t)j2 * 32 + l];

    float4 acc;
    acc.x = fmaf(a0, s.x, fmaf(c0, w0.x, fmaf(c1, w1.x, c2 * w2.x)));
    acc.y = fmaf(a0, s.y, fmaf(c0, w0.y, fmaf(c1, w1.y, c2 * w2.y)));
    acc.z = fmaf(a0, s.z, fmaf(c0, w0.z, fmaf(c1, w1.z, c2 * w2.z)));
    acc.w = fmaf(a0, s.w, fmaf(c0, w0.w, fmaf(c1, w1.w, c2 * w2.w)));
    ((float4*)&sm[t * HC])[l] = acc;
    __syncthreads();

    // transpose write: out[b][i][o][t], float4 along t
    int g = threadIdx.x >> 7;          // 0..5
    int o = threadIdx.x & 127;
    float4 v;
    v.x = sm[(4 * g + 0) * HC + o];
    v.y = sm[(4 * g + 1) * HC + o];
    v.z = sm[(4 * g + 2) * HC + o];
    v.w = sm[(4 * g + 3) * HC + o];
    float* ob = out + ((size_t)(b * NN + i) * HC + o) * TT;
    ((float4*)ob)[g] = v;
}

// ================= launch =================
extern "C" void kernel_launch(void* const* d_in, const int* in_sizes, int n_in,
                              void* d_out, int out_size) {
    const float* x    = (const float*)d_in[0];  // (B, N, F_IN, T)
    const float* Ww   = (const float*)d_in[1];  // (HC, F_IN)
    const float* Wb   = (const float*)d_in[2];  // (HC,)
    const float* attn = (const float*)d_in[3];  // (H, 2C)
    const float* iw   = (const float*)d_in[4];  // (N, N)
    const float* base = (const float*)d_in[5];  // (N, N)
    const float* mask = (const float*)d_in[6];  // (N, N)
    float* out = (float*)d_out;                 // (B, N, HC, T)
    (void)in_sizes; (void)n_in; (void)out_size;

    k0_neighbors<<<NN, 32>>>(iw, base, mask);
    k1_wh<<<BB * NN, HC>>>(x, Ww, Wb, attn);
    k2_colsum<<<BB * TT, 512>>>();
    k3_out<<<BB * NN, 768>>>(out);
}

// round 14
// speedup vs baseline: 2.3403x; 1.1207x over previous
#include <cuda_runtime.h>
#include <math.h>
#include <stdint.h>

#define BB  8
#define NN  325
#define FIN 32
#define TT  24
#define HH  4
#define CC  32
#define HC  128
#define KMAX 8
#define NPAIR 163   // ceil(NN/2)

// -------- scratch (device globals; no allocation allowed) --------
__device__ float  g_Wh  [(size_t)BB * TT * NN * HC];   // [bt][n][o]  ~32MB
__device__ float  g_f1  [(size_t)BB * TT * NN * HH];   // [bt][n][h]
__device__ float  g_f2  [(size_t)BB * TT * NN * HH];
__device__ float  g_Sall[(size_t)BB * TT * HC];        // [bt][o]
__device__ int    g_nidx[NN * KMAX];
__device__ float  g_nw  [NN * KMAX];
__device__ int    g_ncnt[NN];

// -------- packed f32x2 helpers (Blackwell FFMA2 via PTX only) --------
__device__ __forceinline__ uint64_t pack2(float v) {
    uint64_t r; unsigned u = __float_as_uint(v);
    asm("mov.b64 %0, {%1, %1};" : "=l"(r) : "r"(u));
    return r;
}
__device__ __forceinline__ void fma2(uint64_t& d, uint64_t a, uint64_t b) {
    asm("fma.rn.f32x2 %0, %1, %2, %0;" : "+l"(d) : "l"(a), "l"(b));
}
__device__ __forceinline__ void unpack2(uint64_t v, float& lo, float& hi) {
    unsigned a, b;
    asm("mov.b64 {%0, %1}, %2;" : "=r"(a), "=r"(b) : "l"(v));
    lo = __uint_as_float(a); hi = __uint_as_float(b);
}

// ================= K0: constrain weights + neighbor compaction =================
__global__ void k0_neighbors(const float* __restrict__ iw,
                             const float* __restrict__ base,
                             const float* __restrict__ mask) {
    int i    = blockIdx.x;
    int lane = threadIdx.x;
    __shared__ int   s_idx[KMAX];
    __shared__ float s_val[KMAX];
    if (lane < KMAX) { s_idx[lane] = 0; s_val[lane] = 0.f; }
    __syncwarp();

    float s   = 0.f;
    int   cnt = 0;
    for (int jb = 0; jb < NN; jb += 32) {
        int j = jb + lane;
        float m = 0.f, mv = 0.f;
        if (j < NN) {
            m = mask[i * NN + j];
            float w  = iw  [i * NN + j];
            float bb = base[i * NN + j];
            float v = fminf(fmaxf(w, 0.5f * bb), 1.5f * bb);
            v = fmaxf(v, 0.f);
            mv = v * m;
        }
        s += mv;
        unsigned bal = __ballot_sync(0xffffffffu, m != 0.f);
        if (m != 0.f) {
            int pos = cnt + __popc(bal & ((1u << lane) - 1u));
            if (pos < KMAX) { s_idx[pos] = j; s_val[pos] = mv; }
        }
        cnt += __popc(bal);
    }
    #pragma unroll
    for (int off = 16; off; off >>= 1) s += __shfl_xor_sync(0xffffffffu, s, off);
    if (s == 0.f) s = 1e-6f;
    __syncwarp();

    cnt = min(cnt, KMAX);
    if (lane == 0) g_ncnt[i] = cnt;
    if (lane < KMAX) {
        g_nidx[i * KMAX + lane] = (lane < cnt) ? s_idx[lane] : 0;
        g_nw  [i * KMAX + lane] = (lane < cnt) ? s_val[lane] / s : 0.f;
    }
}

// ================= K1: Wh = xp @ W^T + b (FFMA2), f1/f2 via folded vectors ===
// 256 threads = 2 n per block. threadIdx>>7 selects the n of the pair.
__global__ void __launch_bounds__(256) k1_wh(const float* __restrict__ x,
                                             const float* __restrict__ Ww,
                                             const float* __restrict__ Wb,
                                             const float* __restrict__ attn) {
    int blk  = blockIdx.x;
    int b    = blk / NPAIR, np = blk % NPAIR;
    int half = threadIdx.x >> 7;
    int o    = threadIdx.x & 127;
    int n    = np * 2 + half;
    bool valid = (n < NN);

    __shared__ __align__(16) float x_sm[2][FIN * TT];  // [half][f][t]
    __shared__ float W_sm[HC * 33];                    // padded
    __shared__ float u1_sm[HC], u2_sm[HC];             // [h][f]
    __shared__ float beta_sm[8];                       // [sel][h]

    if (valid) {
        const float4* xb = (const float4*)(x + ((size_t)b * NN + n) * (FIN * TT));
        float4* xs = (float4*)x_sm[half];
        #pragma unroll
        for (int idx = o; idx < 192; idx += 128) xs[idx] = xb[idx];
    }
    {
        const float4* wsrc = (const float4*)Ww;
        for (int idx = threadIdx.x; idx < 1024; idx += 256) {
            float4 v = wsrc[idx];
            int oo = idx >> 3, ff = (idx & 7) * 4;
            float* dst = &W_sm[oo * 33 + ff];
            dst[0] = v.x; dst[1] = v.y; dst[2] = v.z; dst[3] = v.w;
        }
    }
    __syncthreads();

    // folded attention vectors u1/u2 (threads of half 0 only)
    if (half == 0) {
        int hh = o >> 5, f = o & 31;
        const float* arow = attn + hh * (2 * CC);
        float s1 = 0.f, s2 = 0.f;
        #pragma unroll
        for (int cc = 0; cc < CC; cc++) {
            float wv = W_sm[(hh * 32 + cc) * 33 + f];
            s1 = fmaf(wv, __ldg(&arow[cc]),      s1);
            s2 = fmaf(wv, __ldg(&arow[CC + cc]), s2);
        }
        u1_sm[o] = s1; u2_sm[o] = s2;
        if (o < 8) {
            int sel = o >> 2, hh2 = o & 3;
            float bsum = 0.f;
            #pragma unroll
            for (int cc = 0; cc < CC; cc++)
                bsum = fmaf(__ldg(&Wb[hh2 * 32 + cc]),
                            __ldg(&attn[hh2 * (2 * CC) + sel * CC + cc]), bsum);
            beta_sm[o] = bsum;
        }
    }

    // ---- main GEMM: 12 packed f32x2 accumulators over t ----
    float wreg[FIN];
    #pragma unroll
    for (int f = 0; f < FIN; f++) wreg[f] = W_sm[o * 33 + f];

    uint64_t bias2 = pack2(Wb[o]);
    uint64_t acc2[12];
    #pragma unroll
    for (int q = 0; q < 12; q++) acc2[q] = bias2;

    #pragma unroll
    for (int f = 0; f < FIN; f++) {
        uint64_t wv2 = pack2(wreg[f]);
        const ulonglong2* xr = (const ulonglong2*)&x_sm[half][f * TT];
        #pragma unroll
        for (int q = 0; q < 6; q++) {
            ulonglong2 v = xr[q];
            fma2(acc2[2 * q],     v.x, wv2);
            fma2(acc2[2 * q + 1], v.y, wv2);
        }
    }

    if (valid) {
        #pragma unroll
        for (int q = 0; q < 12; q++) {
            float lo, hi;
            unpack2(acc2[q], lo, hi);
            size_t base0 = ((size_t)(b * TT + 2 * q) * NN + n) * HC + o;
            g_Wh[base0] = lo;
            g_Wh[base0 + (size_t)NN * HC] = hi;
        }
    }
    __syncthreads();   // u/beta ready for epilogue

    // f1/f2: (sel in {0,1}) x (h 0..3) x (t 0..23) per n
    if (valid) {
        #pragma unroll
        for (int idx = o; idx < 192; idx += 128) {
            int sel = idx / 96;
            int rem = idx - sel * 96;
            int tt2 = rem % 24;
            int hh  = rem / 24;
            const float* u = sel ? &u2_sm[hh * 32] : &u1_sm[hh * 32];
            float v = beta_sm[sel * 4 + hh];
            #pragma unroll
            for (int f = 0; f < FIN; f++) v = fmaf(x_sm[half][f * TT + tt2], u[f], v);
            size_t fb = ((size_t)(b * TT + tt2) * NN + n) * HH + hh;
            if (sel) g_f2[fb] = v; else g_f1[fb] = v;
        }
    }
}

// ================= K2: S_all[bt][o] = sum_n Wh[bt][n][o], LDG.128 ============
__global__ void __launch_bounds__(512) k2_colsum() {
    int bt = blockIdx.x;
    int l  = threadIdx.x & 31;       // float4 lane over o
    int q  = threadIdx.x >> 5;       // 0..15 n-slice
    __shared__ float4 red[16][32];

    int n0 = q * 21;
    int n1 = min(NN, n0 + 21);
    const float4* base = (const float4*)(g_Wh + (size_t)bt * NN * HC) + l;
    float4 a = make_float4(0.f, 0.f, 0.f, 0.f);
    for (int n = n0; n < n1; n++) {
        float4 v = base[(size_t)n * 32];
        a.x += v.x; a.y += v.y; a.z += v.z; a.w += v.w;
    }
    red[q][l] = a;
    __syncthreads();
    if (threadIdx.x < 32) {
        float4 s = red[0][l];
        #pragma unroll
        for (int k = 1; k < 16; k++) {
            float4 v = red[k][l];
            s.x += v.x; s.y += v.y; s.z += v.z; s.w += v.w;
        }
        ((float4*)(g_Sall + (size_t)bt * HC))[l] = s;
    }
}

// ================= K3: fused coef + gather-FMA + transpose ====================
// Block = (b,i), 768 threads = 24 warps (warp = t). Every lane computes the
// coefficient quad for its own head (redundant but divergence/shuffle free).
__global__ void __launch_bounds__(768) k3_out(float* __restrict__ out) {
    int blk = blockIdx.x;
    int b = blk / NN, i = blk % NN;
    __shared__ float sm[TT * HC];      // [t][o]

    int t = threadIdx.x >> 5;          // 0..23
    int l = threadIdx.x & 31;
    int h = l >> 3;
    int bt = b * TT + t;

    int j0 = g_nidx[i * KMAX + 0];
    int j1 = g_nidx[i * KMAX + 1];
    int j2 = g_nidx[i * KMAX + 2];
    int cnt = min(g_ncnt[i], 3);
    float nw0 = g_nw[i * KMAX + 0];
    float nw1 = g_nw[i * KMAX + 1];
    float nw2 = g_nw[i * KMAX + 2];

    // bulk gathers first — overlap L2 latency with coefficient math below
    const float4* wh = (const float4*)(g_Wh + (size_t)bt * NN * HC);
    float4 s  = ((const float4*)(g_Sall + (size_t)bt * HC))[l];
    float4 w0 = wh[(size_t)j0 * 32 + l];
    float4 w1 = wh[(size_t)j1 * 32 + l];
    float4 w2 = wh[(size_t)j2 * 32 + l];

    // coefficients (all lanes; h = l>>3; cnt is block-uniform)
    const float* f2b = g_f2 + (size_t)bt * NN * HH;
    float f1i = g_f1[((size_t)bt * NN + i) * HH + h];
    float m = 0.f, s0 = 0.f, s1 = 0.f, s2 = 0.f;
    if (0 < cnt) {
        float e = f1i + f2b[j0 * HH + h];
        s0 = ((e > 0.f) ? e : 0.2f * e) + nw0; m = fmaxf(m, s0);
    }
    if (1 < cnt) {
        float e = f1i + f2b[j1 * HH + h];
        s1 = ((e > 0.f) ? e : 0.2f * e) + nw1; m = fmaxf(m, s1);
    }
    if (2 < cnt) {
        float e = f1i + f2b[j2 * HH + h];
        s2 = ((e > 0.f) ? e : 0.2f * e) + nw2; m = fmaxf(m, s2);
    }
    float E0  = __expf(-m);
    float Ek0 = (0 < cnt) ? __expf(s0 - m) : 0.f;
    float Ek1 = (1 < cnt) ? __expf(s1 - m) : 0.f;
    float Ek2 = (2 < cnt) ? __expf(s2 - m) : 0.f;
    float denom = (float)(NN - cnt) * E0 + Ek0 + Ek1 + Ek2;
    float rd = 1.f / denom;
    float a0 = E0 * rd;
    float c0 = (0 < cnt) ? (Ek0 - E0) * rd : 0.f;
    float c1 = (1 < cnt) ? (Ek1 - E0) * rd : 0.f;
    float c2 = (2 < cnt) ? (Ek2 - E0) * rd : 0.f;

    float4 acc;
    acc.x = fmaf(a0, s.x, fmaf(c0, w0.x, fmaf(c1, w1.x, c2 * w2.x)));
    acc.y = fmaf(a0, s.y, fmaf(c0, w0.y, fmaf(c1, w1.y, c2 * w2.y)));
    acc.z = fmaf(a0, s.z, fmaf(c0, w0.z, fmaf(c1, w1.z, c2 * w2.z)));
    acc.w = fmaf(a0, s.w, fmaf(c0, w0.w, fmaf(c1, w1.w, c2 * w2.w)));
    ((float4*)&sm[t * HC])[l] = acc;
    __syncthreads();

    // transpose write: out[b][i][o][t], float4 along t
    int g = threadIdx.x >> 7;          // 0..5
    int o = threadIdx.x & 127;
    float4 v;
    v.x = sm[(4 * g + 0) * HC + o];
    v.y = sm[(4 * g + 1) * HC + o];
    v.z = sm[(4 * g + 2) * HC + o];
    v.w = sm[(4 * g + 3) * HC + o];
    float* ob = out + ((size_t)(b * NN + i) * HC + o) * TT;
    ((float4*)ob)[g] = v;
}

// ================= launch =================
extern "C" void kernel_launch(void* const* d_in, const int* in_sizes, int n_in,
                              void* d_out, int out_size) {
    const float* x    = (const float*)d_in[0];  // (B, N, F_IN, T)
    const float* Ww   = (const float*)d_in[1];  // (HC, F_IN)
    const float* Wb   = (const float*)d_in[2];  // (HC,)
    const float* attn = (const float*)d_in[3];  // (H, 2C)
    const float* iw   = (const float*)d_in[4];  // (N, N)
    const float* base = (const float*)d_in[5];  // (N, N)
    const float* mask = (const float*)d_in[6];  // (N, N)
    float* out = (float*)d_out;                 // (B, N, HC, T)
    (void)in_sizes; (void)n_in; (void)out_size;

    k0_neighbors<<<NN, 32>>>(iw, base, mask);
    k1_wh<<<BB * NPAIR, 256>>>(x, Ww, Wb, attn);
    k2_colsum<<<BB * TT, 512>>>();
    k3_out<<<BB * NN, 768>>>(out);
}